// round 12
// baseline (speedup 1.0000x reference)
#include <cuda_runtime.h>

#define D       128
#define MMAX    65536
#define QMAX    32
#define NEG_INF_F (-1e30f)
#define MARGIN  0.1f
#define NBLK_SEL 128

// ---------------- scratch (device globals; statically zero-initialized) -----
__device__ float    g_sims[(size_t)MMAX * QMAX];   // only candidate rows written/read
__device__ uint2    g_rowinfo[MMAX];               // {pos_bits, negcand_bits}
__device__ unsigned g_pos_table[65536];            // zero at load; cleared by k_select
__device__ unsigned g_neg_table[65536];
__device__ int      g_maxp[QMAX];
__device__ int      g_maxn[QMAX];
__device__ unsigned g_haspos;
__device__ float    g_part[(size_t)NBLK_SEL * QMAX * 4];

// order-preserving float <-> int encoding (atomicMax-able over negatives)
__device__ __forceinline__ int encf(float f) {
    int i = __float_as_int(f);
    return i >= 0 ? i : i ^ 0x7FFFFFFF;
}
__device__ __forceinline__ float decf(int i) {
    return __int_as_float(i >= 0 ? i : i ^ 0x7FFFFFFF);
}

// packed f32x2 FMA (Blackwell; only reachable via PTX)
__device__ __forceinline__ unsigned long long fma2(
    unsigned long long a, unsigned long long b, unsigned long long c) {
    unsigned long long d;
    asm("fma.rn.f32x2 %0, %1, %2, %3;" : "=l"(d) : "l"(a), "l"(b), "l"(c));
    return d;
}

// ---------------- kernel 1: build tables + init maxima/haspos ---------------
__global__ void k_setup(const long long* __restrict__ targets_col,
                        const long long* __restrict__ qidxs,
                        const long long* __restrict__ pidxs,
                        const long long* __restrict__ nnegs,
                        int Q, int P, int Nn, int triplet_len) {
    __shared__ int jloc[QMAX];
    int tid = threadIdx.x;
    if (tid < Q) {
        long long qid = targets_col[(long long)tid * triplet_len];
        int j = 0;
        for (int k = 0; k < Q; k++) {
            if (qidxs[k] == qid) { j = k; break; }
        }
        jloc[tid] = j;
        g_maxp[tid] = encf(NEG_INF_F);
        g_maxn[tid] = encf(NEG_INF_F);
    }
    if (tid == 0) g_haspos = 0u;
    __syncthreads();
    for (int i = tid; i < Q * P; i += blockDim.x) {
        int q = i / P, p = i % P;
        int id = ((int)pidxs[(long long)jloc[q] * P + p]) & 0xFFFF;
        atomicOr(&g_pos_table[id], 1u << q);
    }
    for (int i = tid; i < Q * Nn; i += blockDim.x) {
        int q = i / Nn, p = i % Nn;
        int id = ((int)nnegs[(long long)jloc[q] * Nn + p]) & 0xFFFF;
        atomicOr(&g_neg_table[id], 1u << q);
    }
}

// ---------------- kernel 2: sims GEMM + maxima + candidate compression ------
// Tile: 64 rows x 32 queries per block. 8 warps x 8 rows, lane = query.
#define SIMS_ROWS 64
#define SQ_STRIDE 33   // padded to break STS transpose conflicts
__global__ void __launch_bounds__(256, 4) k_sims(
    const float* __restrict__ col, const float* __restrict__ rows,
    const long long* __restrict__ tgt_row,
    int m, int Q, int triplet_len)
{
    extern __shared__ unsigned long long smem_raw[];
    ulonglong2* sq = reinterpret_cast<ulonglong2*>(smem_raw);        // [k4][q] stride 33
    ulonglong2* sr = sq + 32 * SQ_STRIDE;                            // [r][k4] stride 32
    int* st    = reinterpret_cast<int*>(sr + SIMS_ROWS * 32);
    int* smaxp = st + SIMS_ROWS;
    int* smaxn = smaxp + QMAX;
    unsigned* shas = reinterpret_cast<unsigned*>(smaxn + QMAX);

    int tid  = threadIdx.x;
    int row0 = blockIdx.x * SIMS_ROWS;

    // stage query vectors: sq[k4][q] (coalesced gmem read, padded smem write)
#pragma unroll
    for (int it = 0; it < 4; it++) {
        int idx = tid + it * 256;           // 1024 items
        int q = idx >> 5, k4 = idx & 31;
        ulonglong2 v = make_ulonglong2(0ull, 0ull);
        if (q < Q)
            v = reinterpret_cast<const ulonglong2*>(
                    col + (size_t)q * triplet_len * D)[k4];
        sq[k4 * SQ_STRIDE + q] = v;
    }
    // stage rows: sr[r][k4] (coalesced both sides)
#pragma unroll
    for (int it = 0; it < (SIMS_ROWS * 32) / 256; it++) {
        int idx = tid + it * 256;
        int r = idx >> 5, k4 = idx & 31;
        ulonglong2 v = make_ulonglong2(0ull, 0ull);
        if (row0 + r < m)
            v = reinterpret_cast<const ulonglong2*>(
                    rows + (size_t)(row0 + r) * D)[k4];
        sr[r * 32 + k4] = v;
    }
    if (tid < SIMS_ROWS)
        st[tid] = (row0 + tid < m) ? (((int)tgt_row[row0 + tid]) & 0xFFFF) : 0;
    if (tid < QMAX) { smaxp[tid] = encf(NEG_INF_F); smaxn[tid] = encf(NEG_INF_F); }
    if (tid == 0) *shas = 0u;
    __syncthreads();

    int warp = tid >> 5, lane = tid & 31;
    int rbase = warp * 8;

    unsigned long long acc[8];
#pragma unroll
    for (int r = 0; r < 8; r++) acc[r] = 0ull;

#pragma unroll 8
    for (int k4 = 0; k4 < 32; k4++) {
        ulonglong2 q2 = sq[k4 * SQ_STRIDE + lane];
#pragma unroll
        for (int r = 0; r < 8; r++) {
            ulonglong2 r2 = sr[(rbase + r) * 32 + k4];  // broadcast
            acc[r] = fma2(q2.x, r2.x, acc[r]);
            acc[r] = fma2(q2.y, r2.y, acc[r]);
        }
    }

    int mp = encf(NEG_INF_F), mn = encf(NEG_INF_F);
    unsigned has = 0u;
#pragma unroll
    for (int r = 0; r < 8; r++) {
        int rr = row0 + rbase + r;
        bool valid = rr < m;
        float2 f = *reinterpret_cast<float2*>(&acc[r]);
        float s = f.x + f.y;
        unsigned pos = valid ? g_pos_table[st[rbase + r]] : 0u;  // warp-uniform
        unsigned neg = valid ? g_neg_table[st[rbase + r]] : 0u;
        bool inq = (lane < Q) && valid;
        bool negok = inq && !((neg >> lane) & 1u);
        int e = encf(s);
        if (inq && ((pos >> lane) & 1u)) mp = max(mp, e);
        if (negok)                        mn = max(mn, e);
        unsigned negc = __ballot_sync(0xffffffffu, negok && s > 0.3f);
        if (valid) {
            if (lane == 0) g_rowinfo[rr] = make_uint2(pos, negc);
            if (pos | negc) g_sims[(size_t)rr * QMAX + lane] = s;
            has |= pos;
        }
    }
    atomicMax(&smaxp[lane], mp);
    atomicMax(&smaxn[lane], mn);
    if (lane == 0) atomicOr(shas, has);
    __syncthreads();
    if (tid < Q) {
        atomicMax(&g_maxp[tid], smaxp[tid]);
        atomicMax(&g_maxn[tid], smaxn[tid]);
    }
    if (tid == 0) atomicOr(&g_haspos, *shas);
}

// ---------------- kernel 3: sparse selection + table clear ------------------
// 128 blocks x 8 warps; each warp scans 32-row chunks of rowinfo (8B/lane),
// processes only candidate rows. Fixed iteration order => deterministic.
__global__ void __launch_bounds__(256) k_select(int m, int Q)
{
    __shared__ float red[8][QMAX][4];
    int tid = threadIdx.x, warp = tid >> 5, lane = tid & 31;
    int gw = blockIdx.x * 8 + warp;
    int nwarps = NBLK_SEL * 8;

    // clear id tables for the next call (tables are not used in this kernel)
    {
        int g = blockIdx.x * 256 + tid;
        for (int i = g; i < 65536; i += NBLK_SEL * 256) {
            g_pos_table[i] = 0u;
            g_neg_table[i] = 0u;
        }
    }

    float thrp = 0.f, thrn = 1e30f;
    if (lane < Q) {
        thrp = decf(g_maxn[lane]) + MARGIN;               // pos_sel: s <  thrp
        thrn = fmaxf(0.4f, decf(g_maxp[lane])) - MARGIN;  // neg_sel: s >  thrn
    }

    float psum = 0.f, pscnt = 0.f, nsum = 0.f, nscnt = 0.f;
    int nchunks = (m + 31) / 32;
    for (int c = gw; c < nchunks; c += nwarps) {
        int row = c * 32 + lane;
        uint2 info = (row < m) ? g_rowinfo[row] : make_uint2(0u, 0u);
        unsigned act = __ballot_sync(0xffffffffu, (info.x | info.y) != 0u);
        while (act) {
            int j = __ffs(act) - 1;
            act &= act - 1;
            unsigned pb = __shfl_sync(0xffffffffu, info.x, j);
            unsigned nb = __shfl_sync(0xffffffffu, info.y, j);
            float s = g_sims[(size_t)(c * 32 + j) * QMAX + lane];
            if (((pb >> lane) & 1u) && s < thrp) { psum += 1.f - s; pscnt += 1.f; }
            if (((nb >> lane) & 1u) && s > thrn) { nsum += s; nscnt += 1.f; }
        }
    }
    red[warp][lane][0] = psum;  red[warp][lane][1] = pscnt;
    red[warp][lane][2] = nsum;  red[warp][lane][3] = nscnt;
    __syncthreads();
    if (warp == 0) {
        float a0 = 0.f, a1 = 0.f, a2 = 0.f, a3 = 0.f;
#pragma unroll
        for (int w = 0; w < 8; w++) {   // fixed order => deterministic
            a0 += red[w][lane][0]; a1 += red[w][lane][1];
            a2 += red[w][lane][2]; a3 += red[w][lane][3];
        }
        float* p = &g_part[((size_t)blockIdx.x * QMAX + lane) * 4];
        p[0] = a0; p[1] = a1; p[2] = a2; p[3] = a3;
    }
}

// ---------------- kernel 4: final deterministic reduction -------------------
__global__ void k_final(float* __restrict__ out, int Q, int nblk) {
    __shared__ float red[8][QMAX][4];
    __shared__ float terms[QMAX];
    int tid = threadIdx.x;
    int chunk = tid >> 5, q = tid & 31;
    int per = nblk / 8;

    float a0 = 0.f, a1 = 0.f, a2 = 0.f, a3 = 0.f;
    for (int b = chunk * per; b < (chunk + 1) * per; b++) {  // fixed order
        const float* p = &g_part[((size_t)b * QMAX + q) * 4];
        a0 += p[0]; a1 += p[1]; a2 += p[2]; a3 += p[3];
    }
    red[chunk][q][0] = a0; red[chunk][q][1] = a1;
    red[chunk][q][2] = a2; red[chunk][q][3] = a3;
    if (tid < QMAX) terms[tid] = 0.f;
    __syncthreads();

    if (tid < Q) {
        float psum = 0.f, pscnt = 0.f, nsum = 0.f, nscnt = 0.f;
#pragma unroll
        for (int c = 0; c < 8; c++) {   // fixed order
            psum += red[c][tid][0]; pscnt += red[c][tid][1];
            nsum += red[c][tid][2]; nscnt += red[c][tid][3];
        }
        float pl = (pscnt > 0.f) ? psum / pscnt : 0.f;
        float nl = (nscnt > 0.f) ? nsum / nscnt : 0.f;
        bool haspos = (g_haspos >> tid) & 1u;
        terms[tid] = haspos ? (pl + nl) : 0.f;
    }
    __syncthreads();
    if (tid == 0) {
        float loss = 0.f;
        for (int i = 0; i < Q; i++) loss += terms[i];
        out[0] = loss / (float)Q;
    }
}

// ---------------- launcher ---------------------------------------------------
extern "C" void kernel_launch(void* const* d_in, const int* in_sizes, int n_in,
                              void* d_out, int out_size) {
    const float*     col   = (const float*)d_in[0];      // inputs_col [n, 128]
    const float*     row   = (const float*)d_in[1];      // inputs_row [m, 128]
    const long long* tcol  = (const long long*)d_in[2];  // targets_col [n]
    const long long* trow  = (const long long*)d_in[3];  // targets_row [m]
    const long long* qidxs = (const long long*)d_in[4];  // [Q]
    const long long* pidxs = (const long long*)d_in[5];  // [Q, P]
    const long long* nnegs = (const long long*)d_in[6];  // [Q, Nn]
    (void)n_in; (void)out_size;

    int n  = in_sizes[2];
    int m  = in_sizes[3];
    int Q  = in_sizes[4];
    int P  = in_sizes[5] / Q;
    int Nn = in_sizes[6] / Q;
    int tl = n / Q;                   // triplet_len = nNeg + 2

    // dynamic smem for k_sims: sq (33-padded) + sr + st + maxima + haspos
    size_t smem_bytes = (32 * SQ_STRIDE + SIMS_ROWS * 32) * sizeof(ulonglong2)
                      + (SIMS_ROWS + 2 * QMAX + 1) * sizeof(int);
    static bool attr_set = false;
    if (!attr_set) {
        cudaFuncSetAttribute(k_sims, cudaFuncAttributeMaxDynamicSharedMemorySize,
                             (int)smem_bytes);
        attr_set = true;
    }

    k_setup<<<1, 256>>>(tcol, qidxs, pidxs, nnegs, Q, P, Nn, tl);
    k_sims<<<(m + SIMS_ROWS - 1) / SIMS_ROWS, 256, smem_bytes>>>(col, row, trow, m, Q, tl);
    k_select<<<NBLK_SEL, 256>>>(m, Q);
    k_final<<<1, 256>>>((float*)d_out, Q, NBLK_SEL);
}

// round 13
// speedup vs baseline: 1.4128x; 1.4128x over previous
#include <cuda_runtime.h>
#include <cstdint>

#define D       128
#define MMAX    65536
#define QMAX    32
#define NEG_INF_F (-1e30f)
#define MARGIN  0.1f
#define NBLK_SEL 128
#define RPB     256          // rows per k_sims block
#define SUB     64           // subtile rows (pipeline stage)
#define NSUB    (RPB / SUB)

// ---------------- scratch (device globals; statically zero-initialized) -----
__device__ float    g_sims[(size_t)MMAX * QMAX];   // candidate rows only
__device__ uint2    g_rowinfo[MMAX];               // {pos_bits, negcand_bits}
__device__ unsigned g_pos_table[65536];            // zero at load; cleared by k_select
__device__ unsigned g_neg_table[65536];
__device__ int      g_maxp[QMAX];
__device__ int      g_maxn[QMAX];
__device__ unsigned g_haspos;
__device__ float    g_part[(size_t)NBLK_SEL * QMAX * 4];
__device__ int      g_ctr;                         // last-block-done counter

// order-preserving float <-> int encoding (atomicMax-able over negatives)
__device__ __forceinline__ int encf(float f) {
    int i = __float_as_int(f);
    return i >= 0 ? i : i ^ 0x7FFFFFFF;
}
__device__ __forceinline__ float decf(int i) {
    return __int_as_float(i >= 0 ? i : i ^ 0x7FFFFFFF);
}

// packed f32x2 FMA (Blackwell; only reachable via PTX)
__device__ __forceinline__ unsigned long long fma2(
    unsigned long long a, unsigned long long b, unsigned long long c) {
    unsigned long long d;
    asm("fma.rn.f32x2 %0, %1, %2, %3;" : "=l"(d) : "l"(a), "l"(b), "l"(c));
    return d;
}

__device__ __forceinline__ void cp16(uint32_t saddr, const void* gptr) {
    asm volatile("cp.async.cg.shared.global [%0], [%1], 16;" :: "r"(saddr), "l"(gptr));
}

// ---------------- kernel 1: build tables + init maxima/haspos ---------------
__global__ void k_setup(const long long* __restrict__ targets_col,
                        const long long* __restrict__ qidxs,
                        const long long* __restrict__ pidxs,
                        const long long* __restrict__ nnegs,
                        int Q, int P, int Nn, int triplet_len) {
    __shared__ int jloc[QMAX];
    int tid = threadIdx.x;
    if (tid < Q) {
        long long qid = targets_col[(long long)tid * triplet_len];
        int j = 0;
        for (int k = 0; k < Q; k++) {
            if (qidxs[k] == qid) { j = k; break; }
        }
        jloc[tid] = j;
        g_maxp[tid] = encf(NEG_INF_F);
        g_maxn[tid] = encf(NEG_INF_F);
    }
    if (tid == 0) g_haspos = 0u;
    __syncthreads();
    for (int i = tid; i < Q * P; i += blockDim.x) {
        int q = i / P, p = i % P;
        int id = ((int)pidxs[(long long)jloc[q] * P + p]) & 0xFFFF;
        atomicOr(&g_pos_table[id], 1u << q);
    }
    for (int i = tid; i < Q * Nn; i += blockDim.x) {
        int q = i / Nn, p = i % Nn;
        int id = ((int)nnegs[(long long)jloc[q] * Nn + p]) & 0xFFFF;
        atomicOr(&g_neg_table[id], 1u << q);
    }
}

// ---------------- kernel 2: pipelined sims GEMM + maxima + compression ------
// 256 rows/block: queries staged once, rows streamed as 4x64-row cp.async
// double-buffered subtiles. 8 warps x 8 rows per subtile, lane = query.
#define SQ_STRIDE 33
__global__ void __launch_bounds__(256, 2) k_sims(
    const float* __restrict__ col, const float* __restrict__ rows,
    const long long* __restrict__ tgt_row,
    int m, int Q, int triplet_len)
{
    extern __shared__ unsigned long long smem_raw[];
    ulonglong2* sq = reinterpret_cast<ulonglong2*>(smem_raw);   // [k4][q] stride 33
    ulonglong2* sr = sq + 32 * SQ_STRIDE;                       // [2][SUB][32]
    int* st    = reinterpret_cast<int*>(sr + 2 * SUB * 32);     // [RPB]
    int* smaxp = st + RPB;
    int* smaxn = smaxp + QMAX;
    unsigned* shas = reinterpret_cast<unsigned*>(smaxn + QMAX);

    uint32_t sr_base = (uint32_t)__cvta_generic_to_shared(sr);

    int tid  = threadIdx.x;
    int row0 = blockIdx.x * RPB;
    int warp = tid >> 5, lane = tid & 31;
    int rbase = warp * 8;

    // stage query vectors: sq[k4][q]
#pragma unroll
    for (int it = 0; it < 4; it++) {
        int idx = tid + it * 256;           // 1024 items
        int q = idx >> 5, k4 = idx & 31;
        ulonglong2 v = make_ulonglong2(0ull, 0ull);
        if (q < Q)
            v = reinterpret_cast<const ulonglong2*>(
                    col + (size_t)q * triplet_len * D)[k4];
        sq[k4 * SQ_STRIDE + q] = v;
    }
    // stage targets for all 256 rows
    st[tid] = (row0 + tid < m) ? (((int)tgt_row[row0 + tid]) & 0xFFFF) : 0;
    if (tid < QMAX) { smaxp[tid] = encf(NEG_INF_F); smaxn[tid] = encf(NEG_INF_F); }
    if (tid == 0) *shas = 0u;

    // prefetch subtile 0
    {
#pragma unroll
        for (int it = 0; it < (SUB * 32) / 256; it++) {
            int idx = tid + it * 256;
            int r = idx >> 5, k4 = idx & 31;
            if (row0 + r < m)
                cp16(sr_base + (uint32_t)((r * 32 + k4) * 16),
                     rows + (size_t)(row0 + r) * D + k4 * 4);
        }
        asm volatile("cp.async.commit_group;");
    }

    int mp = encf(NEG_INF_F), mn = encf(NEG_INF_F);
    unsigned has = 0u;

#pragma unroll
    for (int s = 0; s < NSUB; s++) {
        // issue next subtile's loads into the other buffer
        if (s + 1 < NSUB) {
            int buf = (s + 1) & 1;
            int rofs = (s + 1) * SUB;
#pragma unroll
            for (int it = 0; it < (SUB * 32) / 256; it++) {
                int idx = tid + it * 256;
                int r = idx >> 5, k4 = idx & 31;
                if (row0 + rofs + r < m)
                    cp16(sr_base + (uint32_t)(((buf * SUB + r) * 32 + k4) * 16),
                         rows + (size_t)(row0 + rofs + r) * D + k4 * 4);
            }
            asm volatile("cp.async.commit_group;");
            asm volatile("cp.async.wait_group 1;");
        } else {
            asm volatile("cp.async.wait_group 0;");
        }
        __syncthreads();

        const ulonglong2* srb = sr + (s & 1) * SUB * 32;

        unsigned long long acc[8];
#pragma unroll
        for (int r = 0; r < 8; r++) acc[r] = 0ull;

#pragma unroll 2
        for (int k4 = 0; k4 < 32; k4++) {
            ulonglong2 q2 = sq[k4 * SQ_STRIDE + lane];
#pragma unroll
            for (int r = 0; r < 8; r++) {
                ulonglong2 r2 = srb[(rbase + r) * 32 + k4];   // broadcast
                acc[r] = fma2(q2.x, r2.x, acc[r]);
                acc[r] = fma2(q2.y, r2.y, acc[r]);
            }
        }

        // epilogue for this subtile
#pragma unroll
        for (int r = 0; r < 8; r++) {
            int lr = s * SUB + rbase + r;     // row within block
            int rr = row0 + lr;               // global row
            bool valid = rr < m;
            float2 f = *reinterpret_cast<float2*>(&acc[r]);
            float sv = f.x + f.y;
            unsigned pos = valid ? g_pos_table[st[lr]] : 0u;   // warp-uniform
            unsigned neg = valid ? g_neg_table[st[lr]] : 0u;
            bool inq = (lane < Q) && valid;
            bool negok = inq && !((neg >> lane) & 1u);
            int e = encf(sv);
            if (inq && ((pos >> lane) & 1u)) mp = max(mp, e);
            if (negok)                        mn = max(mn, e);
            unsigned negc = __ballot_sync(0xffffffffu, negok && sv > 0.3f);
            if (valid) {
                if (lane == 0) g_rowinfo[rr] = make_uint2(pos, negc);
                if (pos | negc) g_sims[(size_t)rr * QMAX + lane] = sv;
                has |= pos;
            }
        }
        __syncthreads();   // protect buffer reuse by next iteration's cp.async
    }

    atomicMax(&smaxp[lane], mp);
    atomicMax(&smaxn[lane], mn);
    if (lane == 0) atomicOr(shas, has);
    __syncthreads();
    if (tid < Q) {
        atomicMax(&g_maxp[tid], smaxp[tid]);
        atomicMax(&g_maxn[tid], smaxn[tid]);
    }
    if (tid == 0) atomicOr(&g_haspos, *shas);
}

// ---------------- kernel 3: sparse selection + fused final reduction --------
__global__ void __launch_bounds__(256) k_select(float* __restrict__ out,
                                                int m, int Q)
{
    __shared__ float red[8][QMAX][4];
    __shared__ float terms[QMAX];
    __shared__ unsigned slast;
    int tid = threadIdx.x, warp = tid >> 5, lane = tid & 31;
    int gw = blockIdx.x * 8 + warp;
    int nwarps = NBLK_SEL * 8;

    // clear id tables for the next call (not used in this kernel)
    {
        int g = blockIdx.x * 256 + tid;
        for (int i = g; i < 65536; i += NBLK_SEL * 256) {
            g_pos_table[i] = 0u;
            g_neg_table[i] = 0u;
        }
    }

    float thrp = 0.f, thrn = 1e30f;
    if (lane < Q) {
        thrp = decf(g_maxn[lane]) + MARGIN;               // pos_sel: s <  thrp
        thrn = fmaxf(0.4f, decf(g_maxp[lane])) - MARGIN;  // neg_sel: s >  thrn
    }

    float psum = 0.f, pscnt = 0.f, nsum = 0.f, nscnt = 0.f;
    int nchunks = (m + 31) / 32;
    for (int c = gw; c < nchunks; c += nwarps) {
        int row = c * 32 + lane;
        uint2 info = (row < m) ? g_rowinfo[row] : make_uint2(0u, 0u);
        unsigned act = __ballot_sync(0xffffffffu, (info.x | info.y) != 0u);
        while (act) {
            int j = __ffs(act) - 1;
            act &= act - 1;
            unsigned pb = __shfl_sync(0xffffffffu, info.x, j);
            unsigned nb = __shfl_sync(0xffffffffu, info.y, j);
            float s = g_sims[(size_t)(c * 32 + j) * QMAX + lane];
            if (((pb >> lane) & 1u) && s < thrp) { psum += 1.f - s; pscnt += 1.f; }
            if (((nb >> lane) & 1u) && s > thrn) { nsum += s; nscnt += 1.f; }
        }
    }
    red[warp][lane][0] = psum;  red[warp][lane][1] = pscnt;
    red[warp][lane][2] = nsum;  red[warp][lane][3] = nscnt;
    __syncthreads();
    if (warp == 0) {
        float a0 = 0.f, a1 = 0.f, a2 = 0.f, a3 = 0.f;
#pragma unroll
        for (int w = 0; w < 8; w++) {   // fixed order => deterministic
            a0 += red[w][lane][0]; a1 += red[w][lane][1];
            a2 += red[w][lane][2]; a3 += red[w][lane][3];
        }
        float4* p = reinterpret_cast<float4*>(
            &g_part[((size_t)blockIdx.x * QMAX + lane) * 4]);
        *p = make_float4(a0, a1, a2, a3);
        __threadfence();             // order g_part writes before the counter
    }
    __syncthreads();
    if (tid == 0) slast = (atomicAdd(&g_ctr, 1) == NBLK_SEL - 1) ? 1u : 0u;
    __syncthreads();
    if (!slast) return;

    // ---- final reduction (last block only; fixed order => deterministic) ----
    {
        int chunk = tid >> 5, q = tid & 31;        // 8 chunks x 32 queries
        const float4* gp = reinterpret_cast<const float4*>(g_part);
        float a0 = 0.f, a1 = 0.f, a2 = 0.f, a3 = 0.f;
#pragma unroll
        for (int i = 0; i < NBLK_SEL / 8; i++) {   // 16, unrolled -> MLP
            float4 v = __ldcg(&gp[(size_t)(chunk * (NBLK_SEL / 8) + i) * QMAX + q]);
            a0 += v.x; a1 += v.y; a2 += v.z; a3 += v.w;
        }
        __syncthreads();                           // red[] reuse
        red[chunk][q][0] = a0; red[chunk][q][1] = a1;
        red[chunk][q][2] = a2; red[chunk][q][3] = a3;
        if (tid < QMAX) terms[tid] = 0.f;
        __syncthreads();
        if (tid < Q) {
            float s0 = 0.f, s1 = 0.f, s2 = 0.f, s3 = 0.f;
#pragma unroll
            for (int c2 = 0; c2 < 8; c2++) {
                s0 += red[c2][tid][0]; s1 += red[c2][tid][1];
                s2 += red[c2][tid][2]; s3 += red[c2][tid][3];
            }
            float pl = (s1 > 0.f) ? s0 / s1 : 0.f;
            float nl = (s3 > 0.f) ? s2 / s3 : 0.f;
            bool haspos = (g_haspos >> tid) & 1u;
            terms[tid] = haspos ? (pl + nl) : 0.f;
        }
        __syncthreads();
        if (tid == 0) {
            float loss = 0.f;
            for (int i = 0; i < Q; i++) loss += terms[i];
            out[0] = loss / (float)Q;
            g_ctr = 0;                  // reset for next replay
        }
    }
}

// ---------------- launcher ---------------------------------------------------
extern "C" void kernel_launch(void* const* d_in, const int* in_sizes, int n_in,
                              void* d_out, int out_size) {
    const float*     col   = (const float*)d_in[0];      // inputs_col [n, 128]
    const float*     row   = (const float*)d_in[1];      // inputs_row [m, 128]
    const long long* tcol  = (const long long*)d_in[2];  // targets_col [n]
    const long long* trow  = (const long long*)d_in[3];  // targets_row [m]
    const long long* qidxs = (const long long*)d_in[4];  // [Q]
    const long long* pidxs = (const long long*)d_in[5];  // [Q, P]
    const long long* nnegs = (const long long*)d_in[6];  // [Q, Nn]
    (void)n_in; (void)out_size;

    int n  = in_sizes[2];
    int m  = in_sizes[3];
    int Q  = in_sizes[4];
    int P  = in_sizes[5] / Q;
    int Nn = in_sizes[6] / Q;
    int tl = n / Q;                   // triplet_len = nNeg + 2

    // k_sims smem: sq (33-padded) + double-buffered sr + st + maxima + haspos
    size_t smem_bytes = (32 * SQ_STRIDE + 2 * SUB * 32) * sizeof(ulonglong2)
                      + (RPB + 2 * QMAX + 1) * sizeof(int);
    static bool attr_set = false;
    if (!attr_set) {
        cudaFuncSetAttribute(k_sims, cudaFuncAttributeMaxDynamicSharedMemorySize,
                             (int)smem_bytes);
        attr_set = true;
    }

    k_setup<<<1, 256>>>(tcol, qidxs, pidxs, nnegs, Q, P, Nn, tl);
    k_sims<<<(m + RPB - 1) / RPB, 256, smem_bytes>>>(col, row, trow, m, Q, tl);
    k_select<<<NBLK_SEL, 256>>>((float*)d_out, m, Q);
}

// round 14
// speedup vs baseline: 1.5023x; 1.0634x over previous
#include <cuda_runtime.h>
#include <cstdint>

#define D       128
#define MMAX    65536
#define QMAX    32
#define NEG_INF_F (-1e30f)
#define MARGIN  0.1f
#define NBLK_SEL 128
#define RPB     256          // rows per k_sims block
#define SUB     64           // subtile rows (pipeline stage)
#define NSUB    (RPB / SUB)

// ---------------- scratch (device globals; statically zero-initialized) -----
__device__ float    g_sims[(size_t)MMAX * QMAX];   // candidate rows only
__device__ uint2    g_rowinfo[MMAX];               // {pos_bits, negcand_bits}
__device__ unsigned g_pos_table[65536];            // zero at load; cleared by k_select
__device__ unsigned g_neg_table[65536];
__device__ int      g_maxp[QMAX];
__device__ int      g_maxn[QMAX];
__device__ unsigned g_haspos;
__device__ float    g_part[(size_t)NBLK_SEL * QMAX * 4];
__device__ int      g_ctr;                         // last-block-done counter

// order-preserving float <-> int encoding (atomicMax-able over negatives)
__device__ __forceinline__ int encf(float f) {
    int i = __float_as_int(f);
    return i >= 0 ? i : i ^ 0x7FFFFFFF;
}
__device__ __forceinline__ float decf(int i) {
    return __int_as_float(i >= 0 ? i : i ^ 0x7FFFFFFF);
}

// packed f32x2 FMA (Blackwell; only reachable via PTX)
__device__ __forceinline__ unsigned long long fma2(
    unsigned long long a, unsigned long long b, unsigned long long c) {
    unsigned long long d;
    asm("fma.rn.f32x2 %0, %1, %2, %3;" : "=l"(d) : "l"(a), "l"(b), "l"(c));
    return d;
}

__device__ __forceinline__ void cp16(uint32_t saddr, const void* gptr) {
    asm volatile("cp.async.cg.shared.global [%0], [%1], 16;" :: "r"(saddr), "l"(gptr));
}

// ---------------- kernel 1: build tables + init maxima/haspos ---------------
// All global loads parallel (MLP), all matching done in smem.
__global__ void k_setup(const long long* __restrict__ targets_col,
                        const long long* __restrict__ qidxs,
                        const long long* __restrict__ pidxs,
                        const long long* __restrict__ nnegs,
                        int Q, int P, int Nn, int triplet_len) {
    __shared__ long long sqid[QMAX];    // qidxs values
    __shared__ long long stgt[QMAX];    // per-query target id
    __shared__ int jloc[QMAX];
    int tid = threadIdx.x;

    // parallel stage of the two id arrays (one load per thread)
    if (tid < Q)            sqid[tid] = qidxs[tid];
    else if (tid < 2 * Q)   stgt[tid - Q] = targets_col[(long long)(tid - Q) * triplet_len];
    if (tid < Q) {
        g_maxp[tid] = encf(NEG_INF_F);
        g_maxn[tid] = encf(NEG_INF_F);
    }
    if (tid == 0) g_haspos = 0u;
    __syncthreads();

    // match in smem (fast; no global latency)
    if (tid < Q) {
        long long qid = stgt[tid];
        int j = 0;
        for (int k = 0; k < Q; k++)
            if (sqid[k] == qid) { j = k; break; }
        jloc[tid] = j;
    }
    __syncthreads();

    // scatter: Q*P (=320) + Q*Nn (=800) independent loads, full MLP
    for (int i = tid; i < Q * P; i += blockDim.x) {
        int q = i / P, p = i % P;
        int id = ((int)pidxs[(long long)jloc[q] * P + p]) & 0xFFFF;
        atomicOr(&g_pos_table[id], 1u << q);
    }
    for (int i = tid; i < Q * Nn; i += blockDim.x) {
        int q = i / Nn, p = i % Nn;
        int id = ((int)nnegs[(long long)jloc[q] * Nn + p]) & 0xFFFF;
        atomicOr(&g_neg_table[id], 1u << q);
    }
}

// ---------------- kernel 2: pipelined sims GEMM + maxima + compression ------
// 256 rows/block: queries staged once, rows streamed as 4x64-row cp.async
// double-buffered subtiles. 8 warps x 8 rows per subtile, lane = query.
// Table bits for all 256 rows prefetched to smem at staging time.
#define SQ_STRIDE 33
__global__ void __launch_bounds__(256, 2) k_sims(
    const float* __restrict__ col, const float* __restrict__ rows,
    const long long* __restrict__ tgt_row,
    int m, int Q, int triplet_len)
{
    extern __shared__ unsigned long long smem_raw[];
    ulonglong2* sq = reinterpret_cast<ulonglong2*>(smem_raw);   // [k4][q] stride 33
    ulonglong2* sr = sq + 32 * SQ_STRIDE;                       // [2][SUB][32]
    unsigned* spos = reinterpret_cast<unsigned*>(sr + 2 * SUB * 32);  // [RPB]
    unsigned* sneg = spos + RPB;                                      // [RPB]
    int* smaxp = reinterpret_cast<int*>(sneg + RPB);
    int* smaxn = smaxp + QMAX;
    unsigned* shas = reinterpret_cast<unsigned*>(smaxn + QMAX);

    uint32_t sr_base = (uint32_t)__cvta_generic_to_shared(sr);

    int tid  = threadIdx.x;
    int row0 = blockIdx.x * RPB;
    int warp = tid >> 5, lane = tid & 31;
    int rbase = warp * 8;

    // stage targets + prefetch table bits (own-thread value: no barrier needed)
    {
        int t = (row0 + tid < m) ? (((int)tgt_row[row0 + tid]) & 0xFFFF) : -1;
        spos[tid] = (t >= 0) ? g_pos_table[t] : 0u;
        sneg[tid] = (t >= 0) ? g_neg_table[t] : 0u;
    }

    // prefetch subtile 0 rows
#pragma unroll
    for (int it = 0; it < (SUB * 32) / 256; it++) {
        int idx = tid + it * 256;
        int r = idx >> 5, k4 = idx & 31;
        if (row0 + r < m)
            cp16(sr_base + (uint32_t)((r * 32 + k4) * 16),
                 rows + (size_t)(row0 + r) * D + k4 * 4);
    }
    asm volatile("cp.async.commit_group;");

    // stage query vectors: sq[k4][q]
#pragma unroll
    for (int it = 0; it < 4; it++) {
        int idx = tid + it * 256;           // 1024 items
        int q = idx >> 5, k4 = idx & 31;
        ulonglong2 v = make_ulonglong2(0ull, 0ull);
        if (q < Q)
            v = reinterpret_cast<const ulonglong2*>(
                    col + (size_t)q * triplet_len * D)[k4];
        sq[k4 * SQ_STRIDE + q] = v;
    }
    if (tid < QMAX) { smaxp[tid] = encf(NEG_INF_F); smaxn[tid] = encf(NEG_INF_F); }
    if (tid == 0) *shas = 0u;

    int mp = encf(NEG_INF_F), mn = encf(NEG_INF_F);
    unsigned has = 0u;

#pragma unroll
    for (int s = 0; s < NSUB; s++) {
        // issue next subtile's loads into the other buffer
        if (s + 1 < NSUB) {
            int buf = (s + 1) & 1;
            int rofs = (s + 1) * SUB;
#pragma unroll
            for (int it = 0; it < (SUB * 32) / 256; it++) {
                int idx = tid + it * 256;
                int r = idx >> 5, k4 = idx & 31;
                if (row0 + rofs + r < m)
                    cp16(sr_base + (uint32_t)(((buf * SUB + r) * 32 + k4) * 16),
                         rows + (size_t)(row0 + rofs + r) * D + k4 * 4);
            }
            asm volatile("cp.async.commit_group;");
            asm volatile("cp.async.wait_group 1;");
        } else {
            asm volatile("cp.async.wait_group 0;");
        }
        __syncthreads();

        const ulonglong2* srb = sr + (s & 1) * SUB * 32;

        unsigned long long acc[8];
#pragma unroll
        for (int r = 0; r < 8; r++) acc[r] = 0ull;

#pragma unroll 2
        for (int k4 = 0; k4 < 32; k4++) {
            ulonglong2 q2 = sq[k4 * SQ_STRIDE + lane];
#pragma unroll
            for (int r = 0; r < 8; r++) {
                ulonglong2 r2 = srb[(rbase + r) * 32 + k4];   // broadcast
                acc[r] = fma2(q2.x, r2.x, acc[r]);
                acc[r] = fma2(q2.y, r2.y, acc[r]);
            }
        }

        // epilogue for this subtile (all mask bits come from smem now)
#pragma unroll
        for (int r = 0; r < 8; r++) {
            int lr = s * SUB + rbase + r;     // row within block
            int rr = row0 + lr;               // global row
            bool valid = rr < m;
            float2 f = *reinterpret_cast<float2*>(&acc[r]);
            float sv = f.x + f.y;
            unsigned pos = spos[lr];          // smem broadcast
            unsigned neg = sneg[lr];
            bool inq = (lane < Q) && valid;
            bool negok = inq && !((neg >> lane) & 1u);
            int e = encf(sv);
            if (inq && ((pos >> lane) & 1u)) mp = max(mp, e);
            if (negok)                        mn = max(mn, e);
            unsigned negc = __ballot_sync(0xffffffffu, negok && sv > 0.3f);
            if (valid) {
                if (lane == 0) g_rowinfo[rr] = make_uint2(pos, negc);
                if (pos | negc) g_sims[(size_t)rr * QMAX + lane] = sv;
                has |= pos;
            }
        }
        __syncthreads();   // protect buffer reuse by next iteration's cp.async
    }

    atomicMax(&smaxp[lane], mp);
    atomicMax(&smaxn[lane], mn);
    if (lane == 0) atomicOr(shas, has);
    __syncthreads();
    if (tid < Q) {
        atomicMax(&g_maxp[tid], smaxp[tid]);
        atomicMax(&g_maxn[tid], smaxn[tid]);
    }
    if (tid == 0) atomicOr(&g_haspos, *shas);
}

// ---------------- kernel 3: sparse selection + fused final reduction --------
__global__ void __launch_bounds__(256) k_select(float* __restrict__ out,
                                                int m, int Q)
{
    __shared__ float red[8][QMAX][4];
    __shared__ float terms[QMAX];
    __shared__ unsigned slast;
    int tid = threadIdx.x, warp = tid >> 5, lane = tid & 31;
    int gw = blockIdx.x * 8 + warp;
    int nwarps = NBLK_SEL * 8;

    // clear id tables for the next call (not used in this kernel)
    {
        int g = blockIdx.x * 256 + tid;
        for (int i = g; i < 65536; i += NBLK_SEL * 256) {
            g_pos_table[i] = 0u;
            g_neg_table[i] = 0u;
        }
    }

    float thrp = 0.f, thrn = 1e30f;
    if (lane < Q) {
        thrp = decf(g_maxn[lane]) + MARGIN;               // pos_sel: s <  thrp
        thrn = fmaxf(0.4f, decf(g_maxp[lane])) - MARGIN;  // neg_sel: s >  thrn
    }

    float psum = 0.f, pscnt = 0.f, nsum = 0.f, nscnt = 0.f;
    int nchunks = (m + 31) / 32;
    for (int c = gw; c < nchunks; c += nwarps) {
        int row = c * 32 + lane;
        uint2 info = (row < m) ? g_rowinfo[row] : make_uint2(0u, 0u);
        unsigned act = __ballot_sync(0xffffffffu, (info.x | info.y) != 0u);
        while (act) {
            int j = __ffs(act) - 1;
            act &= act - 1;
            unsigned pb = __shfl_sync(0xffffffffu, info.x, j);
            unsigned nb = __shfl_sync(0xffffffffu, info.y, j);
            float s = g_sims[(size_t)(c * 32 + j) * QMAX + lane];
            if (((pb >> lane) & 1u) && s < thrp) { psum += 1.f - s; pscnt += 1.f; }
            if (((nb >> lane) & 1u) && s > thrn) { nsum += s; nscnt += 1.f; }
        }
    }
    red[warp][lane][0] = psum;  red[warp][lane][1] = pscnt;
    red[warp][lane][2] = nsum;  red[warp][lane][3] = nscnt;
    __syncthreads();
    if (warp == 0) {
        float a0 = 0.f, a1 = 0.f, a2 = 0.f, a3 = 0.f;
#pragma unroll
        for (int w = 0; w < 8; w++) {   // fixed order => deterministic
            a0 += red[w][lane][0]; a1 += red[w][lane][1];
            a2 += red[w][lane][2]; a3 += red[w][lane][3];
        }
        float4* p = reinterpret_cast<float4*>(
            &g_part[((size_t)blockIdx.x * QMAX + lane) * 4]);
        *p = make_float4(a0, a1, a2, a3);
        __threadfence();             // order g_part writes before the counter
    }
    __syncthreads();
    if (tid == 0) slast = (atomicAdd(&g_ctr, 1) == NBLK_SEL - 1) ? 1u : 0u;
    __syncthreads();
    if (!slast) return;

    // ---- final reduction (last block only; fixed order => deterministic) ----
    {
        int chunk = tid >> 5, q = tid & 31;        // 8 chunks x 32 queries
        const float4* gp = reinterpret_cast<const float4*>(g_part);
        float a0 = 0.f, a1 = 0.f, a2 = 0.f, a3 = 0.f;
#pragma unroll
        for (int i = 0; i < NBLK_SEL / 8; i++) {   // 16, unrolled -> MLP
            float4 v = __ldcg(&gp[(size_t)(chunk * (NBLK_SEL / 8) + i) * QMAX + q]);
            a0 += v.x; a1 += v.y; a2 += v.z; a3 += v.w;
        }
        __syncthreads();                           // red[] reuse
        red[chunk][q][0] = a0; red[chunk][q][1] = a1;
        red[chunk][q][2] = a2; red[chunk][q][3] = a3;
        if (tid < QMAX) terms[tid] = 0.f;
        __syncthreads();
        if (tid < Q) {
            float s0 = 0.f, s1 = 0.f, s2 = 0.f, s3 = 0.f;
#pragma unroll
            for (int c2 = 0; c2 < 8; c2++) {
                s0 += red[c2][tid][0]; s1 += red[c2][tid][1];
                s2 += red[c2][tid][2]; s3 += red[c2][tid][3];
            }
            float pl = (s1 > 0.f) ? s0 / s1 : 0.f;
            float nl = (s3 > 0.f) ? s2 / s3 : 0.f;
            bool haspos = (g_haspos >> tid) & 1u;
            terms[tid] = haspos ? (pl + nl) : 0.f;
        }
        __syncthreads();
        if (tid == 0) {
            float loss = 0.f;
            for (int i = 0; i < Q; i++) loss += terms[i];
            out[0] = loss / (float)Q;
            g_ctr = 0;                  // reset for next replay
        }
    }
}

// ---------------- launcher ---------------------------------------------------
extern "C" void kernel_launch(void* const* d_in, const int* in_sizes, int n_in,
                              void* d_out, int out_size) {
    const float*     col   = (const float*)d_in[0];      // inputs_col [n, 128]
    const float*     row   = (const float*)d_in[1];      // inputs_row [m, 128]
    const long long* tcol  = (const long long*)d_in[2];  // targets_col [n]
    const long long* trow  = (const long long*)d_in[3];  // targets_row [m]
    const long long* qidxs = (const long long*)d_in[4];  // [Q]
    const long long* pidxs = (const long long*)d_in[5];  // [Q, P]
    const long long* nnegs = (const long long*)d_in[6];  // [Q, Nn]
    (void)n_in; (void)out_size;

    int n  = in_sizes[2];
    int m  = in_sizes[3];
    int Q  = in_sizes[4];
    int P  = in_sizes[5] / Q;
    int Nn = in_sizes[6] / Q;
    int tl = n / Q;                   // triplet_len = nNeg + 2

    // k_sims smem: sq (33-padded) + double-buffered sr + tables + maxima + haspos
    size_t smem_bytes = (32 * SQ_STRIDE + 2 * SUB * 32) * sizeof(ulonglong2)
                      + (2 * RPB + 2 * QMAX + 1) * sizeof(int);
    static bool attr_set = false;
    if (!attr_set) {
        cudaFuncSetAttribute(k_sims, cudaFuncAttributeMaxDynamicSharedMemorySize,
                             (int)smem_bytes);
        attr_set = true;
    }

    k_setup<<<1, 256>>>(tcol, qidxs, pidxs, nnegs, Q, P, Nn, tl);
    k_sims<<<(m + RPB - 1) / RPB, 256, smem_bytes>>>(col, row, trow, m, Q, tl);
    k_select<<<NBLK_SEL, 256>>>((float*)d_out, m, Q);
}